// round 6
// baseline (speedup 1.0000x reference)
#include <cuda_runtime.h>
#include <cuda_bf16.h>
#include <cstdint>

#define NN 100000
#define EE 1600000
#define DD 128
#define SCAN_T 1024
#define CHUNK  98      // ceil(NN / SCAN_T)

// ---------------- scratch (no allocations allowed) ----------------
__device__ float g_h1 [(size_t)NN * DD];
__device__ float g_agg[(size_t)NN * DD];
__device__ int   g_cnt[NN];
__device__ int   g_off[NN + 1];
__device__ int   g_cur[NN];
__device__ int   g_csr[EE];

// ---------------- CSR build ----------------
__global__ void zero_cnt_kernel(int* __restrict__ cnt) {
    int i = blockIdx.x * blockDim.x + threadIdx.x;
    if (i < NN) cnt[i] = 0;
}

__global__ void hist_kernel(const int* __restrict__ dst, int* __restrict__ cnt, int E) {
    int e = blockIdx.x * blockDim.x + threadIdx.x;
    if (e < E) atomicAdd(&cnt[dst[e]], 1);
}

__global__ __launch_bounds__(SCAN_T) void scan_kernel(const int* __restrict__ cnt,
                                                      int* __restrict__ off,
                                                      int* __restrict__ cur) {
    __shared__ int ssum[SCAN_T];
    int t = threadIdx.x;
    int start = t * CHUNK;
    int s = 0;
    for (int i = 0; i < CHUNK; i++) {
        int idx = start + i;
        if (idx < NN) s += cnt[idx];
    }
    ssum[t] = s;
    __syncthreads();
    for (int d = 1; d < SCAN_T; d <<= 1) {
        int v = (t >= d) ? ssum[t - d] : 0;
        __syncthreads();
        ssum[t] += v;
        __syncthreads();
    }
    int running = (t == 0) ? 0 : ssum[t - 1];
    for (int i = 0; i < CHUNK; i++) {
        int idx = start + i;
        if (idx < NN) {
            off[idx] = running;
            cur[idx] = running;
            running += cnt[idx];
        }
    }
    if (t == SCAN_T - 1) off[NN] = running;
}

__global__ void fill_kernel(const int* __restrict__ src, const int* __restrict__ dst,
                            int* __restrict__ cur, int* __restrict__ csr, int E) {
    int e = blockIdx.x * blockDim.x + threadIdx.x;
    if (e < E) {
        int pos = atomicAdd(&cur[dst[e]], 1);
        csr[pos] = src[e];
    }
}

// ---------------- mean gather: PERSISTENT, warp per node (strided) ----------------
#define GATHER_BLOCKS (148 * 4)
__global__ __launch_bounds__(256, 4) void gather_kernel(
    const float* __restrict__ x,     // [N,128]
    const int* __restrict__ off,     // [N+1]
    const int* __restrict__ csr,     // [E]
    float* __restrict__ agg)         // [N,128] <- mean
{
    const int lane = threadIdx.x & 31;
    const int warp0 = (blockIdx.x * blockDim.x + threadIdx.x) >> 5;
    const int nwarps = (GATHER_BLOCKS * 256) >> 5;
    const float4* x4 = (const float4*)x;

    for (int gw = warp0; gw < NN; gw += nwarps) {
        int beg = __ldg(&off[gw]);
        int end = __ldg(&off[gw + 1]);

        float4 acc = make_float4(0.f, 0.f, 0.f, 0.f);
        int j = beg;
        int full = beg + ((end - beg) & ~7);
        #pragma unroll 1
        for (; j < full; j += 8) {
            int s0 = __ldg(&csr[j + 0]);
            int s1 = __ldg(&csr[j + 1]);
            int s2 = __ldg(&csr[j + 2]);
            int s3 = __ldg(&csr[j + 3]);
            int s4 = __ldg(&csr[j + 4]);
            int s5 = __ldg(&csr[j + 5]);
            int s6 = __ldg(&csr[j + 6]);
            int s7 = __ldg(&csr[j + 7]);
            float4 v0 = __ldg(&x4[(size_t)s0 * 32 + lane]);
            float4 v1 = __ldg(&x4[(size_t)s1 * 32 + lane]);
            float4 v2 = __ldg(&x4[(size_t)s2 * 32 + lane]);
            float4 v3 = __ldg(&x4[(size_t)s3 * 32 + lane]);
            float4 v4 = __ldg(&x4[(size_t)s4 * 32 + lane]);
            float4 v5 = __ldg(&x4[(size_t)s5 * 32 + lane]);
            float4 v6 = __ldg(&x4[(size_t)s6 * 32 + lane]);
            float4 v7 = __ldg(&x4[(size_t)s7 * 32 + lane]);
            acc.x += (v0.x + v1.x) + (v2.x + v3.x) + (v4.x + v5.x) + (v6.x + v7.x);
            acc.y += (v0.y + v1.y) + (v2.y + v3.y) + (v4.y + v5.y) + (v6.y + v7.y);
            acc.z += (v0.z + v1.z) + (v2.z + v3.z) + (v4.z + v5.z) + (v6.z + v7.z);
            acc.w += (v0.w + v1.w) + (v2.w + v3.w) + (v4.w + v5.w) + (v6.w + v7.w);
        }
        #pragma unroll 1
        for (; j < end; j++) {
            int s = __ldg(&csr[j]);
            float4 v = __ldg(&x4[(size_t)s * 32 + lane]);
            acc.x += v.x; acc.y += v.y; acc.z += v.z; acc.w += v.w;
        }
        float inv = 1.0f / fmaxf((float)(end - beg), 1.0f);
        ((float4*)agg)[(size_t)gw * 32 + lane] =
            make_float4(acc.x * inv, acc.y * inv, acc.z * inv, acc.w * inv);
    }
}

// ======================= tf32 mma.sync GEMM layer =======================
// out[0:N,0:128] = relu?( [x | mean] @ [Ws ; Wn] + b )   (K = 256, tf32)
// Tile: 128 nodes x 128 cols per block, 8 warps in 4x2 (warp: 32 rows x 64 cols).

__device__ __forceinline__ uint32_t f2tf32(float f) {
    uint32_t u;
    asm("cvt.rna.tf32.f32 %0, %1;" : "=r"(u) : "f"(f));
    return u;
}

#define MMA_TF32(c, a, b)                                                        \
    asm volatile("mma.sync.aligned.m16n8k8.row.col.f32.tf32.tf32.f32 "           \
                 "{%0,%1,%2,%3}, {%4,%5,%6,%7}, {%8,%9}, {%0,%1,%2,%3};"         \
                 : "+f"((c)[0]), "+f"((c)[1]), "+f"((c)[2]), "+f"((c)[3])        \
                 : "r"((a)[0]), "r"((a)[1]), "r"((a)[2]), "r"((a)[3]),           \
                   "r"((b)[0]), "r"((b)[1]))

#define ASTRIDE 132   // floats per A row (bank-conflict-free: 132 % 32 == 4)
#define BSTRIDE 260   // floats per B row (260 % 32 == 4), holds k=0..255
#define AS_OFF  128                       // floats (after bias)
#define BS_OFF  (AS_OFF + 128 * ASTRIDE)  // 17024
#define SM_FLOATS (BS_OFF + 128 * BSTRIDE)  // 50304 -> 201216 bytes

__global__ __launch_bounds__(256) void layer_mma_kernel(
    const float* __restrict__ x,     // [N,128] self features
    const float* __restrict__ agg,   // [N,128] mean neighbor features
    const float* __restrict__ Ws,    // [128,128] (k, j) row-major
    const float* __restrict__ Wn,    // [128,128]
    const float* __restrict__ bias,  // [128]
    float* __restrict__ out,         // [N,128]
    int do_relu)
{
    extern __shared__ float smem[];
    float* bsm = smem;                          // [128]
    uint32_t* As = (uint32_t*)(smem + AS_OFF);  // [128][ASTRIDE] tf32
    uint32_t* Bs = (uint32_t*)(smem + BS_OFF);  // [128 n][BSTRIDE] tf32 (k-major)
    const int tid = threadIdx.x;
    const int wid = tid >> 5, lane = tid & 31;
    const int g = lane >> 2, tg = lane & 3;
    const int warp_m = wid & 3, warp_n = wid >> 2;
    const int base = blockIdx.x * 128;

    if (tid < 128) bsm[tid] = __ldg(&bias[tid]);

    // ---- stage B = [Ws ; Wn]^T as Bs[n][k] (tf32) ----
    #pragma unroll 4
    for (int idx = tid; idx < 16384; idx += 256) {
        int k = idx >> 7, n = idx & 127;
        Bs[n * BSTRIDE + k]       = f2tf32(__ldg(&Ws[idx]));
        Bs[n * BSTRIDE + 128 + k] = f2tf32(__ldg(&Wn[idx]));
    }

    float c[2][8][4];
    #pragma unroll
    for (int mt = 0; mt < 2; mt++)
        #pragma unroll
        for (int nt = 0; nt < 8; nt++)
            #pragma unroll
            for (int q = 0; q < 4; q++) c[mt][nt][q] = 0.f;

    // ---- two K-passes: pass0 = x (k 0..127), pass1 = mean (k 128..255) ----
    #pragma unroll 1
    for (int pass = 0; pass < 2; pass++) {
        const float4* src4 = (const float4*)(pass ? agg : x);
        __syncthreads();   // previous-pass readers done before As overwrite
        #pragma unroll 4
        for (int idx = tid; idx < 4096; idx += 256) {
            int r = idx >> 5, k4 = idx & 31;
            int node = base + r;
            float4 v = make_float4(0.f, 0.f, 0.f, 0.f);
            if (node < NN) v = __ldg(&src4[(size_t)node * 32 + k4]);
            uint4 u;
            u.x = f2tf32(v.x); u.y = f2tf32(v.y); u.z = f2tf32(v.z); u.w = f2tf32(v.w);
            *(uint4*)&As[r * ASTRIDE + k4 * 4] = u;
        }
        __syncthreads();

        const uint32_t* ap = &As[(warp_m * 32 + g) * ASTRIDE + tg];
        const uint32_t* bp = &Bs[(warp_n * 64 + g) * BSTRIDE + tg + pass * 128];

        #pragma unroll 4
        for (int ks = 0; ks < 16; ks++) {
            const int kb = ks * 8;
            uint32_t a[2][4];
            #pragma unroll
            for (int mt = 0; mt < 2; mt++) {
                const uint32_t* p = ap + mt * 16 * ASTRIDE + kb;
                a[mt][0] = p[0];
                a[mt][1] = p[8 * ASTRIDE];
                a[mt][2] = p[4];
                a[mt][3] = p[8 * ASTRIDE + 4];
            }
            uint32_t b[8][2];
            #pragma unroll
            for (int nt = 0; nt < 8; nt++) {
                const uint32_t* p = bp + nt * 8 * BSTRIDE + kb;
                b[nt][0] = p[0];
                b[nt][1] = p[4];
            }
            #pragma unroll
            for (int mt = 0; mt < 2; mt++)
                #pragma unroll
                for (int nt = 0; nt < 8; nt++)
                    MMA_TF32(c[mt][nt], a[mt], b[nt]);
        }
    }

    // ---- epilogue: bias (+relu), float2 stores ----
    #pragma unroll
    for (int mt = 0; mt < 2; mt++) {
        #pragma unroll
        for (int half = 0; half < 2; half++) {
            int row = warp_m * 32 + mt * 16 + half * 8 + g;
            int node = base + row;
            if (node < NN) {
                float* orow = out + (size_t)node * 128;
                #pragma unroll
                for (int nt = 0; nt < 8; nt++) {
                    int col = warp_n * 64 + nt * 8 + tg * 2;
                    float v0 = c[mt][nt][half * 2 + 0] + bsm[col];
                    float v1 = c[mt][nt][half * 2 + 1] + bsm[col + 1];
                    if (do_relu) { v0 = fmaxf(v0, 0.f); v1 = fmaxf(v1, 0.f); }
                    *(float2*)(orow + col) = make_float2(v0, v1);
                }
            }
        }
    }
}

// ---------------- launch ----------------
extern "C" void kernel_launch(void* const* d_in, const int* in_sizes, int n_in,
                              void* d_out, int out_size) {
    const float* in_feat  = (const float*)d_in[0];
    const float* W1_self  = (const float*)d_in[1];
    const float* W1_neigh = (const float*)d_in[2];
    const float* b1       = (const float*)d_in[3];
    const float* W2_self  = (const float*)d_in[4];
    const float* W2_neigh = (const float*)d_in[5];
    const float* b2       = (const float*)d_in[6];
    const int*   src      = (const int*)d_in[7];
    const int*   dst      = (const int*)d_in[8];
    const int E = in_sizes[7];

    float* out = (float*)d_out;

    float *h1, *agg;
    int *cnt, *off, *cur, *csr;
    cudaGetSymbolAddress((void**)&h1,  g_h1);
    cudaGetSymbolAddress((void**)&agg, g_agg);
    cudaGetSymbolAddress((void**)&cnt, g_cnt);
    cudaGetSymbolAddress((void**)&off, g_off);
    cudaGetSymbolAddress((void**)&cur, g_cur);
    cudaGetSymbolAddress((void**)&csr, g_csr);

    const int smem_bytes = SM_FLOATS * 4;   // 201216
    cudaFuncSetAttribute(layer_mma_kernel, cudaFuncAttributeMaxDynamicSharedMemorySize, smem_bytes);

    const int nb = (NN + 255) / 256;
    const int eb = (E + 255) / 256;
    const int lb = (NN + 127) / 128;          // 128-node tiles

    // ---- CSR build (by dst) ----
    zero_cnt_kernel<<<nb, 256>>>(cnt);
    hist_kernel<<<eb, 256>>>(dst, cnt, E);
    scan_kernel<<<1, SCAN_T>>>(cnt, off, cur);
    fill_kernel<<<eb, 256>>>(src, dst, cur, csr, E);

    // ---- layer 1 ----
    gather_kernel<<<GATHER_BLOCKS, 256>>>(in_feat, off, csr, agg);
    layer_mma_kernel<<<lb, 256, smem_bytes>>>(in_feat, agg, W1_self, W1_neigh, b1, h1, 1);

    // ---- layer 2 ----
    gather_kernel<<<GATHER_BLOCKS, 256>>>(h1, off, csr, agg);
    layer_mma_kernel<<<lb, 256, smem_bytes>>>(h1, agg, W2_self, W2_neigh, b2, out, 0);
}

// round 8
// speedup vs baseline: 1.0002x; 1.0002x over previous
#include <cuda_runtime.h>
#include <cuda_fp16.h>
#include <cstdint>

#define NN 100000
#define EE 1600000
#define DD 128
#define SCAN_T 1024
#define CHUNK  98      // ceil(NN / SCAN_T)

// ---------------- scratch (no allocations allowed) ----------------
__device__ float g_h1 [(size_t)NN * DD];
__device__ float g_agg[(size_t)NN * DD];
__device__ uint2 g_xh [(size_t)NN * 32];   // fp16 shadow of current features (128 halves/row)
__device__ int   g_cnt[NN];
__device__ int   g_off[NN + 1];
__device__ int   g_cur[NN];
__device__ int   g_csr[EE];

// ---------------- CSR build ----------------
__global__ void zero_cnt_kernel(int* __restrict__ cnt) {
    int i = blockIdx.x * blockDim.x + threadIdx.x;
    if (i < NN) cnt[i] = 0;
}

__global__ void hist_kernel(const int* __restrict__ dst, int* __restrict__ cnt, int E) {
    int e = blockIdx.x * blockDim.x + threadIdx.x;
    if (e < E) atomicAdd(&cnt[dst[e]], 1);
}

__global__ __launch_bounds__(SCAN_T) void scan_kernel(const int* __restrict__ cnt,
                                                      int* __restrict__ off,
                                                      int* __restrict__ cur) {
    __shared__ int ssum[SCAN_T];
    int t = threadIdx.x;
    int start = t * CHUNK;
    int s = 0;
    for (int i = 0; i < CHUNK; i++) {
        int idx = start + i;
        if (idx < NN) s += cnt[idx];
    }
    ssum[t] = s;
    __syncthreads();
    for (int d = 1; d < SCAN_T; d <<= 1) {
        int v = (t >= d) ? ssum[t - d] : 0;
        __syncthreads();
        ssum[t] += v;
        __syncthreads();
    }
    int running = (t == 0) ? 0 : ssum[t - 1];
    for (int i = 0; i < CHUNK; i++) {
        int idx = start + i;
        if (idx < NN) {
            off[idx] = running;
            cur[idx] = running;
            running += cnt[idx];
        }
    }
    if (t == SCAN_T - 1) off[NN] = running;
}

__global__ void fill_kernel(const int* __restrict__ src, const int* __restrict__ dst,
                            int* __restrict__ cur, int* __restrict__ csr, int E) {
    int e = blockIdx.x * blockDim.x + threadIdx.x;
    if (e < E) {
        int pos = atomicAdd(&cur[dst[e]], 1);
        csr[pos] = src[e];
    }
}

// ---------------- fp32 -> fp16 feature convert ----------------
__global__ void cvt_kernel(const float4* __restrict__ x4, uint2* __restrict__ xh, int n4) {
    int i = blockIdx.x * blockDim.x + threadIdx.x;
    if (i >= n4) return;
    float4 v = __ldg(&x4[i]);
    __half2 a = __floats2half2_rn(v.x, v.y);
    __half2 b = __floats2half2_rn(v.z, v.w);
    uint2 o;
    o.x = *(uint32_t*)&a;
    o.y = *(uint32_t*)&b;
    xh[i] = o;
}

// ---------------- mean gather (fp16 rows, fp32 accum): warp per node ----------------
__device__ __forceinline__ void acc_u2(float2& a01, float2& a23, uint2 u) {
    float2 f0 = __half22float2(*(__half2*)&u.x);
    float2 f1 = __half22float2(*(__half2*)&u.y);
    a01.x += f0.x; a01.y += f0.y;
    a23.x += f1.x; a23.y += f1.y;
}

__global__ __launch_bounds__(256) void gather_kernel(
    const uint2* __restrict__ xh,    // [N][32] fp16 rows
    const int* __restrict__ off,     // [N+1]
    const int* __restrict__ csr,     // [E]
    float* __restrict__ agg)         // [N,128] <- mean (fp32)
{
    int gw = (blockIdx.x * blockDim.x + threadIdx.x) >> 5;   // node id
    if (gw >= NN) return;
    int lane = threadIdx.x & 31;
    int beg = __ldg(&off[gw]);
    int end = __ldg(&off[gw + 1]);

    float2 a01 = make_float2(0.f, 0.f);
    float2 a23 = make_float2(0.f, 0.f);
    int j = beg;
    int full = beg + ((end - beg) & ~7);
    #pragma unroll 1
    for (; j < full; j += 8) {
        int s0 = __ldg(&csr[j + 0]);
        int s1 = __ldg(&csr[j + 1]);
        int s2 = __ldg(&csr[j + 2]);
        int s3 = __ldg(&csr[j + 3]);
        int s4 = __ldg(&csr[j + 4]);
        int s5 = __ldg(&csr[j + 5]);
        int s6 = __ldg(&csr[j + 6]);
        int s7 = __ldg(&csr[j + 7]);
        uint2 u0 = __ldg(&xh[(size_t)s0 * 32 + lane]);
        uint2 u1 = __ldg(&xh[(size_t)s1 * 32 + lane]);
        uint2 u2 = __ldg(&xh[(size_t)s2 * 32 + lane]);
        uint2 u3 = __ldg(&xh[(size_t)s3 * 32 + lane]);
        uint2 u4 = __ldg(&xh[(size_t)s4 * 32 + lane]);
        uint2 u5 = __ldg(&xh[(size_t)s5 * 32 + lane]);
        uint2 u6 = __ldg(&xh[(size_t)s6 * 32 + lane]);
        uint2 u7 = __ldg(&xh[(size_t)s7 * 32 + lane]);
        acc_u2(a01, a23, u0); acc_u2(a01, a23, u1);
        acc_u2(a01, a23, u2); acc_u2(a01, a23, u3);
        acc_u2(a01, a23, u4); acc_u2(a01, a23, u5);
        acc_u2(a01, a23, u6); acc_u2(a01, a23, u7);
    }
    #pragma unroll 1
    for (; j < end; j++) {
        int s = __ldg(&csr[j]);
        uint2 u = __ldg(&xh[(size_t)s * 32 + lane]);
        acc_u2(a01, a23, u);
    }
    float inv = 1.0f / fmaxf((float)(end - beg), 1.0f);
    ((float4*)agg)[(size_t)gw * 32 + lane] =
        make_float4(a01.x * inv, a01.y * inv, a23.x * inv, a23.y * inv);
}

// ======================= tf32 mma.sync GEMM layer =======================
// out[0:N,0:128] = relu?( [x | mean] @ [Ws ; Wn] + b )   (K = 256, tf32)
// Tile: 128 nodes x 128 cols per block, 8 warps in 4x2 (warp: 32 rows x 64 cols).

__device__ __forceinline__ uint32_t f2tf32(float f) {
    uint32_t u;
    asm("cvt.rna.tf32.f32 %0, %1;" : "=r"(u) : "f"(f));
    return u;
}

#define MMA_TF32(c, a, b)                                                        \
    asm volatile("mma.sync.aligned.m16n8k8.row.col.f32.tf32.tf32.f32 "           \
                 "{%0,%1,%2,%3}, {%4,%5,%6,%7}, {%8,%9}, {%0,%1,%2,%3};"         \
                 : "+f"((c)[0]), "+f"((c)[1]), "+f"((c)[2]), "+f"((c)[3])        \
                 : "r"((a)[0]), "r"((a)[1]), "r"((a)[2]), "r"((a)[3]),           \
                   "r"((b)[0]), "r"((b)[1]))

#define ASTRIDE 132   // floats per A row (bank-conflict-free: 132 % 32 == 4)
#define BSTRIDE 260   // floats per B row (260 % 32 == 4), holds k=0..255
#define AS_OFF  128                       // floats (after bias)
#define BS_OFF  (AS_OFF + 128 * ASTRIDE)  // 17024
#define SM_FLOATS (BS_OFF + 128 * BSTRIDE)  // 50304 -> 201216 bytes

__global__ __launch_bounds__(256) void layer_mma_kernel(
    const float* __restrict__ x,     // [N,128] self features (fp32)
    const float* __restrict__ agg,   // [N,128] mean neighbor features (fp32)
    const float* __restrict__ Ws,    // [128,128] (k, j) row-major
    const float* __restrict__ Wn,    // [128,128]
    const float* __restrict__ bias,  // [128]
    float* __restrict__ out,         // [N,128]
    __half* __restrict__ out_h,      // optional fp16 shadow of out (or nullptr)
    int do_relu)
{
    extern __shared__ float smem[];
    float* bsm = smem;                          // [128]
    uint32_t* As = (uint32_t*)(smem + AS_OFF);  // [128][ASTRIDE] tf32
    uint32_t* Bs = (uint32_t*)(smem + BS_OFF);  // [128 n][BSTRIDE] tf32 (k-major)
    const int tid = threadIdx.x;
    const int wid = tid >> 5, lane = tid & 31;
    const int g = lane >> 2, tg = lane & 3;
    const int warp_m = wid & 3, warp_n = wid >> 2;
    const int base = blockIdx.x * 128;

    if (tid < 128) bsm[tid] = __ldg(&bias[tid]);

    // ---- stage B = [Ws ; Wn]^T as Bs[n][k] (tf32) ----
    #pragma unroll 4
    for (int idx = tid; idx < 16384; idx += 256) {
        int k = idx >> 7, n = idx & 127;
        Bs[n * BSTRIDE + k]       = f2tf32(__ldg(&Ws[idx]));
        Bs[n * BSTRIDE + 128 + k] = f2tf32(__ldg(&Wn[idx]));
    }

    float c[2][8][4];
    #pragma unroll
    for (int mt = 0; mt < 2; mt++)
        #pragma unroll
        for (int nt = 0; nt < 8; nt++)
            #pragma unroll
            for (int q = 0; q < 4; q++) c[mt][nt][q] = 0.f;

    // ---- two K-passes: pass0 = x (k 0..127), pass1 = mean (k 128..255) ----
    #pragma unroll 1
    for (int pass = 0; pass < 2; pass++) {
        const float4* src4 = (const float4*)(pass ? agg : x);
        __syncthreads();   // previous-pass readers done before As overwrite
        #pragma unroll 4
        for (int idx = tid; idx < 4096; idx += 256) {
            int r = idx >> 5, k4 = idx & 31;
            int node = base + r;
            float4 v = make_float4(0.f, 0.f, 0.f, 0.f);
            if (node < NN) v = __ldg(&src4[(size_t)node * 32 + k4]);
            uint4 u;
            u.x = f2tf32(v.x); u.y = f2tf32(v.y); u.z = f2tf32(v.z); u.w = f2tf32(v.w);
            *(uint4*)&As[r * ASTRIDE + k4 * 4] = u;
        }
        __syncthreads();

        const uint32_t* ap = &As[(warp_m * 32 + g) * ASTRIDE + tg];
        const uint32_t* bp = &Bs[(warp_n * 64 + g) * BSTRIDE + tg + pass * 128];

        #pragma unroll 4
        for (int ks = 0; ks < 16; ks++) {
            const int kb = ks * 8;
            uint32_t a[2][4];
            #pragma unroll
            for (int mt = 0; mt < 2; mt++) {
                const uint32_t* p = ap + mt * 16 * ASTRIDE + kb;
                a[mt][0] = p[0];
                a[mt][1] = p[8 * ASTRIDE];
                a[mt][2] = p[4];
                a[mt][3] = p[8 * ASTRIDE + 4];
            }
            uint32_t b[8][2];
            #pragma unroll
            for (int nt = 0; nt < 8; nt++) {
                const uint32_t* p = bp + nt * 8 * BSTRIDE + kb;
                b[nt][0] = p[0];
                b[nt][1] = p[4];
            }
            #pragma unroll
            for (int mt = 0; mt < 2; mt++)
                #pragma unroll
                for (int nt = 0; nt < 8; nt++)
                    MMA_TF32(c[mt][nt], a[mt], b[nt]);
        }
    }

    // ---- epilogue: bias (+relu), float2 stores (+ optional fp16 shadow) ----
    #pragma unroll
    for (int mt = 0; mt < 2; mt++) {
        #pragma unroll
        for (int half = 0; half < 2; half++) {
            int row = warp_m * 32 + mt * 16 + half * 8 + g;
            int node = base + row;
            if (node < NN) {
                float* orow = out + (size_t)node * 128;
                #pragma unroll
                for (int nt = 0; nt < 8; nt++) {
                    int col = warp_n * 64 + nt * 8 + tg * 2;
                    float v0 = c[mt][nt][half * 2 + 0] + bsm[col];
                    float v1 = c[mt][nt][half * 2 + 1] + bsm[col + 1];
                    if (do_relu) { v0 = fmaxf(v0, 0.f); v1 = fmaxf(v1, 0.f); }
                    *(float2*)(orow + col) = make_float2(v0, v1);
                    if (out_h) {
                        __half2 h = __floats2half2_rn(v0, v1);
                        *(__half2*)(out_h + (size_t)node * 128 + col) = h;
                    }
                }
            }
        }
    }
}

// ---------------- launch ----------------
extern "C" void kernel_launch(void* const* d_in, const int* in_sizes, int n_in,
                              void* d_out, int out_size) {
    const float* in_feat  = (const float*)d_in[0];
    const float* W1_self  = (const float*)d_in[1];
    const float* W1_neigh = (const float*)d_in[2];
    const float* b1       = (const float*)d_in[3];
    const float* W2_self  = (const float*)d_in[4];
    const float* W2_neigh = (const float*)d_in[5];
    const float* b2       = (const float*)d_in[6];
    const int*   src      = (const int*)d_in[7];
    const int*   dst      = (const int*)d_in[8];
    const int E = in_sizes[7];

    float* out = (float*)d_out;

    float *h1, *agg;
    uint2 *xh;
    int *cnt, *off, *cur, *csr;
    cudaGetSymbolAddress((void**)&h1,  g_h1);
    cudaGetSymbolAddress((void**)&agg, g_agg);
    cudaGetSymbolAddress((void**)&xh,  g_xh);
    cudaGetSymbolAddress((void**)&cnt, g_cnt);
    cudaGetSymbolAddress((void**)&off, g_off);
    cudaGetSymbolAddress((void**)&cur, g_cur);
    cudaGetSymbolAddress((void**)&csr, g_csr);

    const int smem_bytes = SM_FLOATS * 4;   // 201216
    cudaFuncSetAttribute(layer_mma_kernel, cudaFuncAttributeMaxDynamicSharedMemorySize, smem_bytes);

    const int nb = (NN + 255) / 256;
    const int eb = (E + 255) / 256;
    const int gb = (NN * 32 + 255) / 256;     // warp per node
    const int cb = (NN * 32 + 255) / 256;     // float4 per thread
    const int lb = (NN + 127) / 128;          // 128-node tiles

    // ---- CSR build (by dst) ----
    zero_cnt_kernel<<<nb, 256>>>(cnt);
    hist_kernel<<<eb, 256>>>(dst, cnt, E);
    scan_kernel<<<1, SCAN_T>>>(cnt, off, cur);
    fill_kernel<<<eb, 256>>>(src, dst, cur, csr, E);

    // ---- layer 1 ----
    cvt_kernel<<<cb, 256>>>((const float4*)in_feat, xh, NN * 32);
    gather_kernel<<<gb, 256>>>(xh, off, csr, agg);
    layer_mma_kernel<<<lb, 256, smem_bytes>>>(in_feat, agg, W1_self, W1_neigh, b1,
                                              h1, (__half*)xh, 1);

    // ---- layer 2 ----
    gather_kernel<<<gb, 256>>>(xh, off, csr, agg);
    layer_mma_kernel<<<lb, 256, smem_bytes>>>(h1, agg, W2_self, W2_neigh, b2,
                                              out, nullptr, 0);
}

// round 10
// speedup vs baseline: 1.4402x; 1.4399x over previous
#include <cuda_runtime.h>
#include <cuda_fp16.h>
#include <cstdint>

#define NN 100000
#define EE 1600000
#define DD 128
#define SCAN_T 1024
#define CHUNK  98      // ceil(NN / SCAN_T)

// ---------------- scratch (no allocations allowed) ----------------
__device__ uint2 g_xh  [(size_t)NN * 32];  // fp16 in_feat / layer-1 input (128 halves/row)
__device__ uint2 g_h1h [(size_t)NN * 32];  // fp16 h1
__device__ uint2 g_aggh[(size_t)NN * 32];  // fp16 neighbor mean
__device__ int   g_cnt[NN];
__device__ int   g_off[NN + 1];
__device__ int   g_cur[NN];
__device__ int   g_csr[EE];

// ---------------- CSR build ----------------
__global__ void zero_cnt_kernel(int* __restrict__ cnt) {
    int i = blockIdx.x * blockDim.x + threadIdx.x;
    if (i < NN) cnt[i] = 0;
}

__global__ void hist_kernel(const int* __restrict__ dst, int* __restrict__ cnt, int E) {
    int e = blockIdx.x * blockDim.x + threadIdx.x;
    if (e < E) atomicAdd(&cnt[dst[e]], 1);
}

__global__ __launch_bounds__(SCAN_T) void scan_kernel(const int* __restrict__ cnt,
                                                      int* __restrict__ off,
                                                      int* __restrict__ cur) {
    __shared__ int ssum[SCAN_T];
    int t = threadIdx.x;
    int start = t * CHUNK;
    int s = 0;
    for (int i = 0; i < CHUNK; i++) {
        int idx = start + i;
        if (idx < NN) s += cnt[idx];
    }
    ssum[t] = s;
    __syncthreads();
    for (int d = 1; d < SCAN_T; d <<= 1) {
        int v = (t >= d) ? ssum[t - d] : 0;
        __syncthreads();
        ssum[t] += v;
        __syncthreads();
    }
    int running = (t == 0) ? 0 : ssum[t - 1];
    for (int i = 0; i < CHUNK; i++) {
        int idx = start + i;
        if (idx < NN) {
            off[idx] = running;
            cur[idx] = running;
            running += cnt[idx];
        }
    }
    if (t == SCAN_T - 1) off[NN] = running;
}

__global__ void fill_kernel(const int* __restrict__ src, const int* __restrict__ dst,
                            int* __restrict__ cur, int* __restrict__ csr, int E) {
    int e = blockIdx.x * blockDim.x + threadIdx.x;
    if (e < E) {
        int pos = atomicAdd(&cur[dst[e]], 1);
        csr[pos] = src[e];
    }
}

// ---------------- fp32 -> fp16 feature convert ----------------
__global__ void cvt_kernel(const float4* __restrict__ x4, uint2* __restrict__ xh, int n4) {
    int i = blockIdx.x * blockDim.x + threadIdx.x;
    if (i >= n4) return;
    float4 v = __ldg(&x4[i]);
    __half2 a = __floats2half2_rn(v.x, v.y);
    __half2 b = __floats2half2_rn(v.z, v.w);
    uint2 o;
    o.x = *(uint32_t*)&a;
    o.y = *(uint32_t*)&b;
    xh[i] = o;
}

// ---------------- mean gather (fp16 rows, fp32 accum, fp16 out) ----------------
__device__ __forceinline__ void acc_u2(float2& a01, float2& a23, uint2 u) {
    float2 f0 = __half22float2(*(__half2*)&u.x);
    float2 f1 = __half22float2(*(__half2*)&u.y);
    a01.x += f0.x; a01.y += f0.y;
    a23.x += f1.x; a23.y += f1.y;
}

__global__ __launch_bounds__(256) void gather_kernel(
    const uint2* __restrict__ xh,    // [N][32] fp16 rows
    const int* __restrict__ off,     // [N+1]
    const int* __restrict__ csr,     // [E]
    uint2* __restrict__ aggh)        // [N][32] <- mean (fp16)
{
    int gw = (blockIdx.x * blockDim.x + threadIdx.x) >> 5;   // node id
    if (gw >= NN) return;
    int lane = threadIdx.x & 31;
    int beg = __ldg(&off[gw]);
    int end = __ldg(&off[gw + 1]);

    float2 a01 = make_float2(0.f, 0.f);
    float2 a23 = make_float2(0.f, 0.f);
    int j = beg;
    int full = beg + ((end - beg) & ~7);
    #pragma unroll 1
    for (; j < full; j += 8) {
        int s0 = __ldg(&csr[j + 0]);
        int s1 = __ldg(&csr[j + 1]);
        int s2 = __ldg(&csr[j + 2]);
        int s3 = __ldg(&csr[j + 3]);
        int s4 = __ldg(&csr[j + 4]);
        int s5 = __ldg(&csr[j + 5]);
        int s6 = __ldg(&csr[j + 6]);
        int s7 = __ldg(&csr[j + 7]);
        uint2 u0 = __ldg(&xh[(size_t)s0 * 32 + lane]);
        uint2 u1 = __ldg(&xh[(size_t)s1 * 32 + lane]);
        uint2 u2 = __ldg(&xh[(size_t)s2 * 32 + lane]);
        uint2 u3 = __ldg(&xh[(size_t)s3 * 32 + lane]);
        uint2 u4 = __ldg(&xh[(size_t)s4 * 32 + lane]);
        uint2 u5 = __ldg(&xh[(size_t)s5 * 32 + lane]);
        uint2 u6 = __ldg(&xh[(size_t)s6 * 32 + lane]);
        uint2 u7 = __ldg(&xh[(size_t)s7 * 32 + lane]);
        acc_u2(a01, a23, u0); acc_u2(a01, a23, u1);
        acc_u2(a01, a23, u2); acc_u2(a01, a23, u3);
        acc_u2(a01, a23, u4); acc_u2(a01, a23, u5);
        acc_u2(a01, a23, u6); acc_u2(a01, a23, u7);
    }
    #pragma unroll 1
    for (; j < end; j++) {
        int s = __ldg(&csr[j]);
        uint2 u = __ldg(&xh[(size_t)s * 32 + lane]);
        acc_u2(a01, a23, u);
    }
    float inv = 1.0f / fmaxf((float)(end - beg), 1.0f);
    __half2 h0 = __floats2half2_rn(a01.x * inv, a01.y * inv);
    __half2 h1 = __floats2half2_rn(a23.x * inv, a23.y * inv);
    uint2 o;
    o.x = *(uint32_t*)&h0;
    o.y = *(uint32_t*)&h1;
    aggh[(size_t)gw * 32 + lane] = o;
}

// ======================= fp16 mma.sync GEMM layer =======================
// out[0:N,0:128] = relu?( [x | mean] @ [Ws ; Wn] + b )   (K = 256, fp16 in, fp32 accum)
// Tile: 128 nodes x 128 cols, 8 warps 4x2 (warp: 32 rows x 64 cols), m16n8k16.

#define MMA_F16(c, a, b)                                                         \
    asm volatile("mma.sync.aligned.m16n8k16.row.col.f32.f16.f16.f32 "            \
                 "{%0,%1,%2,%3}, {%4,%5,%6,%7}, {%8,%9}, {%0,%1,%2,%3};"         \
                 : "+f"((c)[0]), "+f"((c)[1]), "+f"((c)[2]), "+f"((c)[3])        \
                 : "r"((a)[0]), "r"((a)[1]), "r"((a)[2]), "r"((a)[3]),           \
                   "r"((b)[0]), "r"((b)[1]))

#define ASTRIDE_H 136   // halves per A row (68 words, 68%32==4 -> conflict-free frags)
#define BSTRIDE_H 264   // halves per B row (132 words, 132%32==4), k=0..255
#define BIAS_BYTES 512
#define AS_BYTES  (128 * ASTRIDE_H * 2)               // 34816
#define BS_OFF_B  (BIAS_BYTES + AS_BYTES)             // 35328
#define SM_BYTES  (BS_OFF_B + 128 * BSTRIDE_H * 2)    // 102912

__global__ __launch_bounds__(256, 2) void layer_mma_kernel(
    const uint2* __restrict__ selfh, // [N][32] fp16 self features
    const uint2* __restrict__ aggh,  // [N][32] fp16 neighbor mean
    const float* __restrict__ Ws,    // [128,128] (k, j) row-major fp32
    const float* __restrict__ Wn,    // [128,128]
    const float* __restrict__ bias,  // [128] fp32
    float* __restrict__ out_f,       // [N,128] fp32 (or nullptr)
    __half* __restrict__ out_h,      // [N,128] fp16 (or nullptr)
    int do_relu)
{
    extern __shared__ char smem[];
    float*  bsm = (float*)smem;                       // [128]
    __half* As  = (__half*)(smem + BIAS_BYTES);       // [128][ASTRIDE_H]
    __half* Bs  = (__half*)(smem + BS_OFF_B);         // [128 n][BSTRIDE_H]
    const int tid = threadIdx.x;
    const int wid = tid >> 5, lane = tid & 31;
    const int g = lane >> 2, tg = lane & 3;
    const int warp_m = wid & 3, warp_n = wid >> 2;
    const int base = blockIdx.x * 128;

    if (tid < 128) bsm[tid] = __ldg(&bias[tid]);

    // ---- stage B = [Ws ; Wn]^T as Bs[n][k] (fp16) ----
    #pragma unroll 4
    for (int idx = tid; idx < 16384; idx += 256) {
        int k = idx >> 7, n = idx & 127;
        Bs[n * BSTRIDE_H + k]       = __float2half_rn(__ldg(&Ws[idx]));
        Bs[n * BSTRIDE_H + 128 + k] = __float2half_rn(__ldg(&Wn[idx]));
    }

    float c[2][8][4];
    #pragma unroll
    for (int mt = 0; mt < 2; mt++)
        #pragma unroll
        for (int nt = 0; nt < 8; nt++)
            #pragma unroll
            for (int q = 0; q < 4; q++) c[mt][nt][q] = 0.f;

    // ---- two K-passes: pass0 = self (k 0..127), pass1 = mean (k 128..255) ----
    #pragma unroll 1
    for (int pass = 0; pass < 2; pass++) {
        const uint4* srcA = (const uint4*)(pass ? aggh : selfh);  // 16B = 8 halves
        __syncthreads();   // previous-pass readers done before As overwrite
        #pragma unroll 8
        for (int idx = tid; idx < 2048; idx += 256) {     // 128 rows x 16 uint4
            int r = idx >> 4, q = idx & 15;
            int node = base + r;
            uint4 v = make_uint4(0u, 0u, 0u, 0u);
            if (node < NN) v = __ldg(&srcA[(size_t)node * 16 + q]);
            *(uint4*)&As[r * ASTRIDE_H + q * 8] = v;
        }
        __syncthreads();

        const __half* arow = &As[(warp_m * 32 + g) * ASTRIDE_H + 2 * tg];
        const __half* brow = &Bs[(warp_n * 64 + g) * BSTRIDE_H + 2 * tg + pass * 128];

        #pragma unroll
        for (int ks = 0; ks < 8; ks++) {                  // K = 128 per pass, k16 steps
            const int kb = ks * 16;
            uint32_t a[2][4];
            #pragma unroll
            for (int mt = 0; mt < 2; mt++) {
                const __half* p = arow + mt * 16 * ASTRIDE_H + kb;
                a[mt][0] = *(const uint32_t*)(p);
                a[mt][1] = *(const uint32_t*)(p + 8 * ASTRIDE_H);
                a[mt][2] = *(const uint32_t*)(p + 8);
                a[mt][3] = *(const uint32_t*)(p + 8 * ASTRIDE_H + 8);
            }
            uint32_t b[8][2];
            #pragma unroll
            for (int nt = 0; nt < 8; nt++) {
                const __half* p = brow + nt * 8 * BSTRIDE_H + kb;
                b[nt][0] = *(const uint32_t*)(p);
                b[nt][1] = *(const uint32_t*)(p + 8);
            }
            #pragma unroll
            for (int mt = 0; mt < 2; mt++)
                #pragma unroll
                for (int nt = 0; nt < 8; nt++)
                    MMA_F16(c[mt][nt], a[mt], b[nt]);
        }
    }

    // ---- epilogue: bias (+relu), fp32 and/or fp16 stores ----
    #pragma unroll
    for (int mt = 0; mt < 2; mt++) {
        #pragma unroll
        for (int half = 0; half < 2; half++) {
            int row = warp_m * 32 + mt * 16 + half * 8 + g;
            int node = base + row;
            if (node < NN) {
                #pragma unroll
                for (int nt = 0; nt < 8; nt++) {
                    int col = warp_n * 64 + nt * 8 + tg * 2;
                    float v0 = c[mt][nt][half * 2 + 0] + bsm[col];
                    float v1 = c[mt][nt][half * 2 + 1] + bsm[col + 1];
                    if (do_relu) { v0 = fmaxf(v0, 0.f); v1 = fmaxf(v1, 0.f); }
                    if (out_f)
                        *(float2*)(out_f + (size_t)node * 128 + col) = make_float2(v0, v1);
                    if (out_h) {
                        __half2 h = __floats2half2_rn(v0, v1);
                        *(__half2*)(out_h + (size_t)node * 128 + col) = h;
                    }
                }
            }
        }
    }
}

// ---------------- launch ----------------
extern "C" void kernel_launch(void* const* d_in, const int* in_sizes, int n_in,
                              void* d_out, int out_size) {
    const float* in_feat  = (const float*)d_in[0];
    const float* W1_self  = (const float*)d_in[1];
    const float* W1_neigh = (const float*)d_in[2];
    const float* b1       = (const float*)d_in[3];
    const float* W2_self  = (const float*)d_in[4];
    const float* W2_neigh = (const float*)d_in[5];
    const float* b2       = (const float*)d_in[6];
    const int*   src      = (const int*)d_in[7];
    const int*   dst      = (const int*)d_in[8];
    const int E = in_sizes[7];

    float* out = (float*)d_out;

    uint2 *xh, *h1h, *aggh;
    int *cnt, *off, *cur, *csr;
    cudaGetSymbolAddress((void**)&xh,   g_xh);
    cudaGetSymbolAddress((void**)&h1h,  g_h1h);
    cudaGetSymbolAddress((void**)&aggh, g_aggh);
    cudaGetSymbolAddress((void**)&cnt,  g_cnt);
    cudaGetSymbolAddress((void**)&off,  g_off);
    cudaGetSymbolAddress((void**)&cur,  g_cur);
    cudaGetSymbolAddress((void**)&csr,  g_csr);

    cudaFuncSetAttribute(layer_mma_kernel, cudaFuncAttributeMaxDynamicSharedMemorySize, SM_BYTES);

    const int nb = (NN + 255) / 256;
    const int eb = (E + 255) / 256;
    const int gb = (NN * 32 + 255) / 256;     // warp per node
    const int cb = (NN * 32 + 255) / 256;
    const int lb = (NN + 127) / 128;          // 128-node tiles

    // ---- CSR build (by dst) ----
    zero_cnt_kernel<<<nb, 256>>>(cnt);
    hist_kernel<<<eb, 256>>>(dst, cnt, E);
    scan_kernel<<<1, SCAN_T>>>(cnt, off, cur);
    fill_kernel<<<eb, 256>>>(src, dst, cur, csr, E);

    // ---- layer 1 ----
    cvt_kernel<<<cb, 256>>>((const float4*)in_feat, xh, NN * 32);
    gather_kernel<<<gb, 256>>>(xh, off, csr, aggh);
    layer_mma_kernel<<<lb, 256, SM_BYTES>>>(xh, aggh, W1_self, W1_neigh, b1,
                                            nullptr, (__half*)h1h, 1);

    // ---- layer 2 ----
    gather_kernel<<<gb, 256>>>(h1h, off, csr, aggh);
    layer_mma_kernel<<<lb, 256, SM_BYTES>>>(h1h, aggh, W2_self, W2_neigh, b2,
                                            out, nullptr, 0);
}

// round 11
// speedup vs baseline: 1.5665x; 1.0877x over previous
#include <cuda_runtime.h>
#include <cuda_fp16.h>
#include <cstdint>

#define NN 100000
#define EE 1600000
#define DD 128
#define SCAN_T 1024
#define CHUNK  98      // ceil(NN / SCAN_T)

// ---------------- scratch (no allocations allowed) ----------------
__device__ uint2  g_xh  [(size_t)NN * 32];  // fp16 in_feat / layer-1 input
__device__ uint2  g_h1h [(size_t)NN * 32];  // fp16 h1
__device__ uint2  g_aggh[(size_t)NN * 32];  // fp16 neighbor mean
__device__ __half g_wt1 [128 * 256];        // layer-1 Wt[n][k] fp16, stacked [Ws|Wn]
__device__ __half g_wt2 [128 * 256];        // layer-2
__device__ int    g_cnt[NN];
__device__ int    g_off[NN + 1];
__device__ int    g_cur[NN];
__device__ int    g_csr[EE];

// ---------------- CSR build ----------------
__global__ void zero_cnt_kernel(int* __restrict__ cnt) {
    int i = blockIdx.x * blockDim.x + threadIdx.x;
    if (i < NN) cnt[i] = 0;
}

__global__ void hist_kernel(const int* __restrict__ dst, int* __restrict__ cnt, int E) {
    int e = blockIdx.x * blockDim.x + threadIdx.x;
    if (e < E) atomicAdd(&cnt[dst[e]], 1);
}

__global__ __launch_bounds__(SCAN_T) void scan_kernel(const int* __restrict__ cnt,
                                                      int* __restrict__ off,
                                                      int* __restrict__ cur) {
    __shared__ int ssum[SCAN_T];
    int t = threadIdx.x;
    int start = t * CHUNK;
    int s = 0;
    for (int i = 0; i < CHUNK; i++) {
        int idx = start + i;
        if (idx < NN) s += cnt[idx];
    }
    ssum[t] = s;
    __syncthreads();
    for (int d = 1; d < SCAN_T; d <<= 1) {
        int v = (t >= d) ? ssum[t - d] : 0;
        __syncthreads();
        ssum[t] += v;
        __syncthreads();
    }
    int running = (t == 0) ? 0 : ssum[t - 1];
    for (int i = 0; i < CHUNK; i++) {
        int idx = start + i;
        if (idx < NN) {
            off[idx] = running;
            cur[idx] = running;
            running += cnt[idx];
        }
    }
    if (t == SCAN_T - 1) off[NN] = running;
}

__global__ void fill_kernel(const int* __restrict__ src, const int* __restrict__ dst,
                            int* __restrict__ cur, int* __restrict__ csr, int E) {
    int e = blockIdx.x * blockDim.x + threadIdx.x;
    if (e < E) {
        int pos = atomicAdd(&cur[dst[e]], 1);
        csr[pos] = src[e];
    }
}

// ---------------- fp32 -> fp16 feature convert ----------------
__global__ void cvt_kernel(const float4* __restrict__ x4, uint2* __restrict__ xh, int n4) {
    int i = blockIdx.x * blockDim.x + threadIdx.x;
    if (i >= n4) return;
    float4 v = __ldg(&x4[i]);
    __half2 a = __floats2half2_rn(v.x, v.y);
    __half2 b = __floats2half2_rn(v.z, v.w);
    uint2 o;
    o.x = *(uint32_t*)&a;
    o.y = *(uint32_t*)&b;
    xh[i] = o;
}

// ---------------- W pre-transpose: Wt[n][k] = W[k][n], fp16, stacked ----------------
__global__ void wprep_kernel(const float* __restrict__ Ws, const float* __restrict__ Wn,
                             __half* __restrict__ wt) {
    __shared__ float tile[32][33];
    int k0 = blockIdx.x * 32, n0 = blockIdx.y * 32;
    int w  = blockIdx.z;                   // 0 = Ws, 1 = Wn
    const float* W = w ? Wn : Ws;
    int tx = threadIdx.x, ty = threadIdx.y;   // (32, 8)
    #pragma unroll
    for (int i = ty; i < 32; i += 8)
        tile[i][tx] = __ldg(&W[(k0 + i) * 128 + n0 + tx]);   // coalesced read (n contig)
    __syncthreads();
    #pragma unroll
    for (int i = ty; i < 32; i += 8)
        wt[(n0 + i) * 256 + w * 128 + k0 + tx] =
            __float2half_rn(tile[tx][i]);                     // coalesced write (k contig)
}

// ---------------- mean gather (fp16 rows, fp32 accum, fp16 out) ----------------
__device__ __forceinline__ void acc_u2(float2& a01, float2& a23, uint2 u) {
    float2 f0 = __half22float2(*(__half2*)&u.x);
    float2 f1 = __half22float2(*(__half2*)&u.y);
    a01.x += f0.x; a01.y += f0.y;
    a23.x += f1.x; a23.y += f1.y;
}

__global__ __launch_bounds__(256) void gather_kernel(
    const uint2* __restrict__ xh,    // [N][32] fp16 rows
    const int* __restrict__ off,     // [N+1]
    const int* __restrict__ csr,     // [E]
    uint2* __restrict__ aggh)        // [N][32] <- mean (fp16)
{
    int gw = (blockIdx.x * blockDim.x + threadIdx.x) >> 5;   // node id
    if (gw >= NN) return;
    int lane = threadIdx.x & 31;
    int beg = __ldg(&off[gw]);
    int end = __ldg(&off[gw + 1]);

    float2 a01 = make_float2(0.f, 0.f);
    float2 a23 = make_float2(0.f, 0.f);
    int j = beg;
    int full = beg + ((end - beg) & ~7);
    #pragma unroll 1
    for (; j < full; j += 8) {
        int s0 = __ldg(&csr[j + 0]);
        int s1 = __ldg(&csr[j + 1]);
        int s2 = __ldg(&csr[j + 2]);
        int s3 = __ldg(&csr[j + 3]);
        int s4 = __ldg(&csr[j + 4]);
        int s5 = __ldg(&csr[j + 5]);
        int s6 = __ldg(&csr[j + 6]);
        int s7 = __ldg(&csr[j + 7]);
        uint2 u0 = __ldg(&xh[(size_t)s0 * 32 + lane]);
        uint2 u1 = __ldg(&xh[(size_t)s1 * 32 + lane]);
        uint2 u2 = __ldg(&xh[(size_t)s2 * 32 + lane]);
        uint2 u3 = __ldg(&xh[(size_t)s3 * 32 + lane]);
        uint2 u4 = __ldg(&xh[(size_t)s4 * 32 + lane]);
        uint2 u5 = __ldg(&xh[(size_t)s5 * 32 + lane]);
        uint2 u6 = __ldg(&xh[(size_t)s6 * 32 + lane]);
        uint2 u7 = __ldg(&xh[(size_t)s7 * 32 + lane]);
        acc_u2(a01, a23, u0); acc_u2(a01, a23, u1);
        acc_u2(a01, a23, u2); acc_u2(a01, a23, u3);
        acc_u2(a01, a23, u4); acc_u2(a01, a23, u5);
        acc_u2(a01, a23, u6); acc_u2(a01, a23, u7);
    }
    #pragma unroll 1
    for (; j < end; j++) {
        int s = __ldg(&csr[j]);
        uint2 u = __ldg(&xh[(size_t)s * 32 + lane]);
        acc_u2(a01, a23, u);
    }
    float inv = 1.0f / fmaxf((float)(end - beg), 1.0f);
    __half2 h0 = __floats2half2_rn(a01.x * inv, a01.y * inv);
    __half2 h1 = __floats2half2_rn(a23.x * inv, a23.y * inv);
    uint2 o;
    o.x = *(uint32_t*)&h0;
    o.y = *(uint32_t*)&h1;
    aggh[(size_t)gw * 32 + lane] = o;
}

// ======================= fp16 mma.sync GEMM layer =======================
// out[0:N,0:128] = relu?( [x | mean] @ Wt^T + b )   (K = 256, fp16 in, fp32 accum)
// Tile: 128 nodes x 128 cols, 8 warps 4x2 (warp: 32 rows x 64 cols), m16n8k16.

#define MMA_F16(c, a, b)                                                         \
    asm volatile("mma.sync.aligned.m16n8k16.row.col.f32.f16.f16.f32 "            \
                 "{%0,%1,%2,%3}, {%4,%5,%6,%7}, {%8,%9}, {%0,%1,%2,%3};"         \
                 : "+f"((c)[0]), "+f"((c)[1]), "+f"((c)[2]), "+f"((c)[3])        \
                 : "r"((a)[0]), "r"((a)[1]), "r"((a)[2]), "r"((a)[3]),           \
                   "r"((b)[0]), "r"((b)[1]))

#define ASTRIDE_H 136   // halves per A row (68 words, 68%32==4 -> conflict-free frags)
#define BSTRIDE_H 264   // halves per B row (132 words, 132%32==4), k=0..255
#define BIAS_BYTES 512
#define AS_BYTES  (128 * ASTRIDE_H * 2)               // 34816
#define BS_OFF_B  (BIAS_BYTES + AS_BYTES)             // 35328
#define SM_BYTES  (BS_OFF_B + 128 * BSTRIDE_H * 2)    // 102912

__global__ __launch_bounds__(256, 2) void layer_mma_kernel(
    const uint2* __restrict__ selfh, // [N][32] fp16 self features
    const uint2* __restrict__ aggh,  // [N][32] fp16 neighbor mean
    const __half* __restrict__ wt,   // [128 n][256 k] fp16 pre-transposed stacked W
    const float* __restrict__ bias,  // [128] fp32
    float* __restrict__ out_f,       // [N,128] fp32 (or nullptr)
    __half* __restrict__ out_h,      // [N,128] fp16 (or nullptr)
    int do_relu)
{
    extern __shared__ char smem[];
    float*  bsm = (float*)smem;                       // [128]
    __half* As  = (__half*)(smem + BIAS_BYTES);       // [128][ASTRIDE_H]
    __half* Bs  = (__half*)(smem + BS_OFF_B);         // [128 n][BSTRIDE_H]
    const int tid = threadIdx.x;
    const int wid = tid >> 5, lane = tid & 31;
    const int g = lane >> 2, tg = lane & 3;
    const int warp_m = wid & 3, warp_n = wid >> 2;
    const int base = blockIdx.x * 128;

    if (tid < 128) bsm[tid] = __ldg(&bias[tid]);

    // ---- stage B: straight uint4 copy of Wt (coalesced LDG, conflict-free STS) ----
    {
        const uint4* wt4 = (const uint4*)wt;          // 4096 uint4 (8 halves each)
        #pragma unroll
        for (int idx = tid; idx < 4096; idx += 256) {
            int n = idx >> 5, kq = idx & 31;          // kq: 8-half chunk along k
            *(uint4*)&Bs[n * BSTRIDE_H + kq * 8] = __ldg(&wt4[idx]);
        }
    }

    float c[2][8][4];
    #pragma unroll
    for (int mt = 0; mt < 2; mt++)
        #pragma unroll
        for (int nt = 0; nt < 8; nt++)
            #pragma unroll
            for (int q = 0; q < 4; q++) c[mt][nt][q] = 0.f;

    // ---- two K-passes: pass0 = self (k 0..127), pass1 = mean (k 128..255) ----
    #pragma unroll 1
    for (int pass = 0; pass < 2; pass++) {
        const uint4* srcA = (const uint4*)(pass ? aggh : selfh);  // 16B = 8 halves
        __syncthreads();   // previous-pass readers done before As overwrite
        #pragma unroll 8
        for (int idx = tid; idx < 2048; idx += 256) {     // 128 rows x 16 uint4
            int r = idx >> 4, q = idx & 15;
            int node = base + r;
            uint4 v = make_uint4(0u, 0u, 0u, 0u);
            if (node < NN) v = __ldg(&srcA[(size_t)node * 16 + q]);
            *(uint4*)&As[r * ASTRIDE_H + q * 8] = v;
        }
        __syncthreads();

        const __half* arow = &As[(warp_m * 32 + g) * ASTRIDE_H + 2 * tg];
        const __half* brow = &Bs[(warp_n * 64 + g) * BSTRIDE_H + 2 * tg + pass * 128];

        #pragma unroll
        for (int ks = 0; ks < 8; ks++) {                  // K = 128 per pass, k16 steps
            const int kb = ks * 16;
            uint32_t a[2][4];
            #pragma unroll
            for (int mt = 0; mt < 2; mt++) {
                const __half* p = arow + mt * 16 * ASTRIDE_H + kb;
                a[mt][0] = *(const uint32_t*)(p);
                a[mt][1] = *(const uint32_t*)(p + 8 * ASTRIDE_H);
                a[mt][2] = *(const uint32_t*)(p + 8);
                a[mt][3] = *(const uint32_t*)(p + 8 * ASTRIDE_H + 8);
            }
            uint32_t b[8][2];
            #pragma unroll
            for (int nt = 0; nt < 8; nt++) {
                const __half* p = brow + nt * 8 * BSTRIDE_H + kb;
                b[nt][0] = *(const uint32_t*)(p);
                b[nt][1] = *(const uint32_t*)(p + 8);
            }
            #pragma unroll
            for (int mt = 0; mt < 2; mt++)
                #pragma unroll
                for (int nt = 0; nt < 8; nt++)
                    MMA_F16(c[mt][nt], a[mt], b[nt]);
        }
    }

    // ---- epilogue: bias (+relu), fp32 and/or fp16 stores ----
    #pragma unroll
    for (int mt = 0; mt < 2; mt++) {
        #pragma unroll
        for (int half = 0; half < 2; half++) {
            int row = warp_m * 32 + mt * 16 + half * 8 + g;
            int node = base + row;
            if (node < NN) {
                #pragma unroll
                for (int nt = 0; nt < 8; nt++) {
                    int col = warp_n * 64 + nt * 8 + tg * 2;
                    float v0 = c[mt][nt][half * 2 + 0] + bsm[col];
                    float v1 = c[mt][nt][half * 2 + 1] + bsm[col + 1];
                    if (do_relu) { v0 = fmaxf(v0, 0.f); v1 = fmaxf(v1, 0.f); }
                    if (out_f)
                        *(float2*)(out_f + (size_t)node * 128 + col) = make_float2(v0, v1);
                    if (out_h) {
                        __half2 h = __floats2half2_rn(v0, v1);
                        *(__half2*)(out_h + (size_t)node * 128 + col) = h;
                    }
                }
            }
        }
    }
}

// ---------------- launch ----------------
extern "C" void kernel_launch(void* const* d_in, const int* in_sizes, int n_in,
                              void* d_out, int out_size) {
    const float* in_feat  = (const float*)d_in[0];
    const float* W1_self  = (const float*)d_in[1];
    const float* W1_neigh = (const float*)d_in[2];
    const float* b1       = (const float*)d_in[3];
    const float* W2_self  = (const float*)d_in[4];
    const float* W2_neigh = (const float*)d_in[5];
    const float* b2       = (const float*)d_in[6];
    const int*   src      = (const int*)d_in[7];
    const int*   dst      = (const int*)d_in[8];
    const int E = in_sizes[7];

    float* out = (float*)d_out;

    uint2 *xh, *h1h, *aggh;
    __half *wt1, *wt2;
    int *cnt, *off, *cur, *csr;
    cudaGetSymbolAddress((void**)&xh,   g_xh);
    cudaGetSymbolAddress((void**)&h1h,  g_h1h);
    cudaGetSymbolAddress((void**)&aggh, g_aggh);
    cudaGetSymbolAddress((void**)&wt1,  g_wt1);
    cudaGetSymbolAddress((void**)&wt2,  g_wt2);
    cudaGetSymbolAddress((void**)&cnt,  g_cnt);
    cudaGetSymbolAddress((void**)&off,  g_off);
    cudaGetSymbolAddress((void**)&cur,  g_cur);
    cudaGetSymbolAddress((void**)&csr,  g_csr);

    cudaFuncSetAttribute(layer_mma_kernel, cudaFuncAttributeMaxDynamicSharedMemorySize, SM_BYTES);

    const int nb = (NN + 255) / 256;
    const int eb = (E + 255) / 256;
    const int gb = (NN * 32 + 255) / 256;     // warp per node
    const int cb = (NN * 32 + 255) / 256;
    const int lb = (NN + 127) / 128;          // 128-node tiles
    dim3 wgrid(4, 4, 2), wblk(32, 8);

    // ---- CSR build (by dst) + weight prep ----
    zero_cnt_kernel<<<nb, 256>>>(cnt);
    hist_kernel<<<eb, 256>>>(dst, cnt, E);
    scan_kernel<<<1, SCAN_T>>>(cnt, off, cur);
    fill_kernel<<<eb, 256>>>(src, dst, cur, csr, E);
    wprep_kernel<<<wgrid, wblk>>>(W1_self, W1_neigh, wt1);
    wprep_kernel<<<wgrid, wblk>>>(W2_self, W2_neigh, wt2);

    // ---- layer 1 ----
    cvt_kernel<<<cb, 256>>>((const float4*)in_feat, xh, NN * 32);
    gather_kernel<<<gb, 256>>>(xh, off, csr, aggh);
    layer_mma_kernel<<<lb, 256, SM_BYTES>>>(xh, aggh, wt1, b1,
                                            nullptr, (__half*)h1h, 1);

    // ---- layer 2 ----
    gather_kernel<<<gb, 256>>>(h1h, off, csr, aggh);
    layer_mma_kernel<<<lb, 256, SM_BYTES>>>(h1h, aggh, wt2, b2,
                                            out, nullptr, 0);
}